// round 2
// baseline (speedup 1.0000x reference)
#include <cuda_runtime.h>

// ---------------------------------------------------------------------------
// AbstractConv3D: 16 levels of dense R^3 grids, 3x3x3 SAME conv, Cin=Cout=16.
// Strategy: one block per 8x8x8 tile (+1 halo), weights for the level in smem,
// 256 threads x 2 voxels/thread, 16 output channels as 8 packed f32x2
// accumulators driven by PTX fma.rn.f32x2 (2x fp32 FMA throughput vs FFMA).
// ---------------------------------------------------------------------------

#define N_TOTAL 1846083
#define N_TILES 4059   // sum over levels of ceil(R/8)^3

__constant__ int c_R[16]    = {16,18,20,22,25,27,30,34,38,42,47,52,58,64,72,80};
__constant__ int c_off[16]  = {0,4096,9928,17928,28576,44201,63884,90884,
                               130188,185060,259148,362971,503579,698691,960835,1334083};
__constant__ int c_Tdim[16] = {2,3,3,3,4,4,4,5,5,6,6,7,8,8,9,10};
// cumulative (inclusive) tile counts per level
__constant__ int c_tcum[16] = {8,35,62,89,153,217,281,406,531,747,963,1306,1818,2330,3059,4059};

__device__ __forceinline__ unsigned long long ffma2(unsigned long long a,
                                                    unsigned long long b,
                                                    unsigned long long c) {
    unsigned long long d;
    asm("fma.rn.f32x2 %0, %1, %2, %3;" : "=l"(d) : "l"(a), "l"(b), "l"(c));
    return d;
}
__device__ __forceinline__ unsigned long long dup2(float x) {
    unsigned long long r;
    asm("mov.b64 %0, {%1, %1};" : "=l"(r) : "f"(x));
    return r;
}
__device__ __forceinline__ unsigned long long pack2(float lo, float hi) {
    unsigned long long r;
    asm("mov.b64 %0, {%1, %2};" : "=l"(r) : "f"(lo), "f"(hi));
    return r;
}

// smem: input halo 10*10*10*16 floats = 16000, weights 27*16*16 = 6912
#define SMEM_IN_FLOATS   16000
#define SMEM_W_FLOATS    6912
#define SMEM_BYTES       ((SMEM_IN_FLOATS + SMEM_W_FLOATS) * 4)

__global__ void __launch_bounds__(256, 2)
conv3d_levels_kernel(const float* __restrict__ input,
                     const float* __restrict__ weight,
                     const float* __restrict__ bias,
                     float* __restrict__ out)
{
    extern __shared__ float smem[];
    float* s_in = smem;                     // [1000][16]
    float* s_w  = smem + SMEM_IN_FLOATS;    // [27][16][16]

    const int t   = blockIdx.x;
    const int b   = blockIdx.y;
    const int tid = threadIdx.x;

    // tile -> level
    int l = 0;
    while (t >= c_tcum[l]) ++l;
    const int base  = l ? c_tcum[l - 1] : 0;
    int local = t - base;
    const int T   = c_Tdim[l];
    const int R   = c_R[l];
    const int off = c_off[l];
    const int tx  = local % T;
    local /= T;
    const int ty  = local % T;
    const int tz  = local / T;
    const int x0 = tx * 8, y0 = ty * 8, z0 = tz * 8;

    // ---- load halo (zeros outside grid = SAME zero padding) ----
    const float* inbase = input + (size_t)b * N_TOTAL * 16;
    for (int h = tid; h < 1000; h += 256) {
        const int hx = h % 10;
        const int hq = h / 10;
        const int hy = hq % 10;
        const int hz = hq / 10;
        const int gx = x0 - 1 + hx;
        const int gy = y0 - 1 + hy;
        const int gz = z0 - 1 + hz;
        float4* dst = (float4*)&s_in[h * 16];
        if ((unsigned)gx < (unsigned)R && (unsigned)gy < (unsigned)R &&
            (unsigned)gz < (unsigned)R) {
            const float4* src = (const float4*)(inbase +
                (size_t)(off + gx + gy * R + gz * R * R) * 16);
            dst[0] = src[0]; dst[1] = src[1]; dst[2] = src[2]; dst[3] = src[3];
        } else {
            const float4 z4 = make_float4(0.f, 0.f, 0.f, 0.f);
            dst[0] = z4; dst[1] = z4; dst[2] = z4; dst[3] = z4;
        }
    }
    // ---- load weights for this level ----
    {
        const float4* wsrc = (const float4*)(weight + (size_t)l * SMEM_W_FLOATS);
        float4* wdst = (float4*)s_w;
        #pragma unroll
        for (int i = tid; i < SMEM_W_FLOATS / 4; i += 256) wdst[i] = wsrc[i];
    }
    __syncthreads();

    // ---- compute: thread owns (x,y,z) and (x,y,z+4) ----
    const int x = tid & 7;
    const int y = (tid >> 3) & 7;
    const int z = tid >> 6;           // 0..3

    unsigned long long acc0[8], acc1[8];
    {
        const float* bp = bias + l * 16;
        #pragma unroll
        for (int j = 0; j < 8; ++j) {
            acc0[j] = pack2(bp[2 * j], bp[2 * j + 1]);
            acc1[j] = acc0[j];
        }
    }

    const int hb0 = (z + 1) * 100 + (y + 1) * 10 + (x + 1);
    const int hb1 = hb0 + 4 * 100;

    #pragma unroll 1
    for (int tap = 0; tap < 27; ++tap) {
        const int dz  = tap / 9;
        const int rem = tap - dz * 9;
        const int dy  = rem / 3;
        const int dx  = rem - dy * 3;
        const int noff = (dz - 1) * 100 + (dy - 1) * 10 + (dx - 1);

        const float4* v0 = (const float4*)&s_in[(hb0 + noff) * 16];
        const float4* v1 = (const float4*)&s_in[(hb1 + noff) * 16];
        const float* wtap = &s_w[tap * 256];

        #pragma unroll
        for (int ci = 0; ci < 4; ++ci) {
            const float4 a0 = v0[ci];
            const float4 a1 = v1[ci];
            const float a0v[4] = {a0.x, a0.y, a0.z, a0.w};
            const float a1v[4] = {a1.x, a1.y, a1.z, a1.w};
            #pragma unroll
            for (int c = 0; c < 4; ++c) {
                const unsigned long long xd0 = dup2(a0v[c]);
                const unsigned long long xd1 = dup2(a1v[c]);
                const ulonglong2* wrow =
                    (const ulonglong2*)&wtap[(ci * 4 + c) * 16];
                #pragma unroll
                for (int q = 0; q < 4; ++q) {
                    const ulonglong2 w = wrow[q];   // 4 couts (2 packed pairs)
                    acc0[2 * q]     = ffma2(xd0, w.x, acc0[2 * q]);
                    acc0[2 * q + 1] = ffma2(xd0, w.y, acc0[2 * q + 1]);
                    acc1[2 * q]     = ffma2(xd1, w.x, acc1[2 * q]);
                    acc1[2 * q + 1] = ffma2(xd1, w.y, acc1[2 * q + 1]);
                }
            }
        }
    }

    // ---- store ----
    const int gx = x0 + x, gy = y0 + y;
    if (gx < R && gy < R) {
        float* outbase = out + (size_t)b * N_TOTAL * 16;
        const int gz0 = z0 + z;
        if (gz0 < R) {
            ulonglong2* o = (ulonglong2*)(outbase +
                (size_t)(off + gx + gy * R + gz0 * R * R) * 16);
            o[0] = make_ulonglong2(acc0[0], acc0[1]);
            o[1] = make_ulonglong2(acc0[2], acc0[3]);
            o[2] = make_ulonglong2(acc0[4], acc0[5]);
            o[3] = make_ulonglong2(acc0[6], acc0[7]);
        }
        const int gz1 = z0 + z + 4;
        if (gz1 < R) {
            ulonglong2* o = (ulonglong2*)(outbase +
                (size_t)(off + gx + gy * R + gz1 * R * R) * 16);
            o[0] = make_ulonglong2(acc1[0], acc1[1]);
            o[1] = make_ulonglong2(acc1[2], acc1[3]);
            o[2] = make_ulonglong2(acc1[4], acc1[5]);
            o[3] = make_ulonglong2(acc1[6], acc1[7]);
        }
    }
}

extern "C" void kernel_launch(void* const* d_in, const int* in_sizes, int n_in,
                              void* d_out, int out_size)
{
    const float* input  = (const float*)d_in[0];
    const float* weight = (const float*)d_in[1];
    const float* bias   = (const float*)d_in[2];
    float* out = (float*)d_out;

    cudaFuncSetAttribute(conv3d_levels_kernel,
                         cudaFuncAttributeMaxDynamicSharedMemorySize, SMEM_BYTES);
    dim3 grid(N_TILES, 2);
    conv3d_levels_kernel<<<grid, 256, SMEM_BYTES>>>(input, weight, bias, out);
}

// round 3
// speedup vs baseline: 1.2515x; 1.2515x over previous
#include <cuda_runtime.h>

// ---------------------------------------------------------------------------
// AbstractConv3D v2: register-blocked. One block per 8x8x8 tile, 128 threads,
// each thread owns a contiguous z-quad of 4 voxels -> weight LDS amortized 2x,
// bank-conflict-free padded smem input layout (stride 20 floats/voxel),
// 16 output channels x 4 voxels as 32 packed f32x2 accumulators (fma.rn.f32x2).
// ---------------------------------------------------------------------------

#define N_TOTAL 1846083
#define N_TILES 4059      // sum over levels of ceil(R/8)^3
#define PAD     20        // floats per voxel in smem halo (16 data + 4 pad)

__constant__ int c_R[16]    = {16,18,20,22,25,27,30,34,38,42,47,52,58,64,72,80};
__constant__ int c_off[16]  = {0,4096,9928,17928,28576,44201,63884,90884,
                               130188,185060,259148,362971,503579,698691,960835,1334083};
__constant__ int c_Tdim[16] = {2,3,3,3,4,4,4,5,5,6,6,7,8,8,9,10};
__constant__ int c_tcum[16] = {8,35,62,89,153,217,281,406,531,747,963,1306,1818,2330,3059,4059};

__device__ __forceinline__ unsigned long long ffma2(unsigned long long a,
                                                    unsigned long long b,
                                                    unsigned long long c) {
    unsigned long long d;
    asm("fma.rn.f32x2 %0, %1, %2, %3;" : "=l"(d) : "l"(a), "l"(b), "l"(c));
    return d;
}
__device__ __forceinline__ unsigned long long dup2(float x) {
    unsigned long long r;
    asm("mov.b64 %0, {%1, %1};" : "=l"(r) : "f"(x));
    return r;
}
__device__ __forceinline__ unsigned long long pack2(float lo, float hi) {
    unsigned long long r;
    asm("mov.b64 %0, {%1, %2};" : "=l"(r) : "f"(lo), "f"(hi));
    return r;
}

#define SMEM_IN_FLOATS (1000 * PAD)           // 20000 floats = 80 KB
#define SMEM_W_FLOATS  6912                   // 27*16*16     = 27.6 KB
#define SMEM_BYTES     ((SMEM_IN_FLOATS + SMEM_W_FLOATS) * 4)

__global__ void __launch_bounds__(128, 2)
conv3d_v2_kernel(const float* __restrict__ input,
                 const float* __restrict__ weight,
                 const float* __restrict__ bias,
                 float* __restrict__ out)
{
    extern __shared__ float smem[];
    float* s_in = smem;                       // [1000][PAD]
    float* s_w  = smem + SMEM_IN_FLOATS;      // [27][16][16]

    const int t   = blockIdx.x;
    const int b   = blockIdx.y;
    const int tid = threadIdx.x;

    // tile -> level
    int l = 0;
    while (t >= c_tcum[l]) ++l;
    const int base  = l ? c_tcum[l - 1] : 0;
    int local = t - base;
    const int T   = c_Tdim[l];
    const int R   = c_R[l];
    const int off = c_off[l];
    const int tx  = local % T;
    local /= T;
    const int ty  = local % T;
    const int tz  = local / T;
    const int x0 = tx * 8, y0 = ty * 8, z0 = tz * 8;

    // ---- load halo (zeros outside grid = SAME zero padding) ----
    const float* inbase = input + (size_t)b * N_TOTAL * 16;
    for (int h = tid; h < 1000; h += 128) {
        const int hx = h % 10;
        const int hq = h / 10;
        const int hy = hq % 10;
        const int hz = hq / 10;
        const int gx = x0 - 1 + hx;
        const int gy = y0 - 1 + hy;
        const int gz = z0 - 1 + hz;
        float* dst = &s_in[h * PAD];
        if ((unsigned)gx < (unsigned)R && (unsigned)gy < (unsigned)R &&
            (unsigned)gz < (unsigned)R) {
            const float4* src = (const float4*)(inbase +
                (size_t)(off + gx + gy * R + gz * R * R) * 16);
            ((float4*)dst)[0] = src[0];
            *(float4*)(dst + 4)  = src[1];
            *(float4*)(dst + 8)  = src[2];
            *(float4*)(dst + 12) = src[3];
        } else {
            const float4 z4 = make_float4(0.f, 0.f, 0.f, 0.f);
            ((float4*)dst)[0] = z4;
            *(float4*)(dst + 4)  = z4;
            *(float4*)(dst + 8)  = z4;
            *(float4*)(dst + 12) = z4;
        }
    }
    // ---- load weights for this level ----
    {
        const float4* wsrc = (const float4*)(weight + (size_t)l * SMEM_W_FLOATS);
        float4* wdst = (float4*)s_w;
        for (int i = tid; i < SMEM_W_FLOATS / 4; i += 128) wdst[i] = wsrc[i];
    }
    __syncthreads();

    // ---- compute: thread (x, y, zh) owns voxels z = 4*zh + {0,1,2,3} ----
    const int x  = tid & 7;
    const int y  = (tid >> 3) & 7;
    const int zh = tid >> 6;          // 0 or 1

    unsigned long long acc[4][8];
    {
        const float* bp = bias + l * 16;
        #pragma unroll
        for (int j = 0; j < 8; ++j) {
            const unsigned long long bj = pack2(bp[2 * j], bp[2 * j + 1]);
            acc[0][j] = bj; acc[1][j] = bj; acc[2][j] = bj; acc[3][j] = bj;
        }
    }

    // halo word index of voxel (x,y, 4*zh): (z+1)*100 + (y+1)*10 + (x+1), times PAD
    const int hbase = ((4 * zh + 1) * 100 + (y + 1) * 10 + (x + 1)) * PAD;
    const int ZSTRIDE = 100 * PAD;    // one z step in the halo

    #pragma unroll 1
    for (int tap = 0; tap < 27; ++tap) {
        const int dz  = tap / 9;
        const int rem = tap - dz * 9;
        const int dy  = rem / 3;
        const int dx  = rem - dy * 3;
        const int noff = ((dz - 1) * 100 + (dy - 1) * 10 + (dx - 1)) * PAD;

        const float* vb   = s_in + hbase + noff;
        const float* wtap = s_w + tap * 256;

        #pragma unroll 1
        for (int ci4 = 0; ci4 < 4; ++ci4) {
            const float4 a0 = *(const float4*)(vb + 0 * ZSTRIDE + ci4 * 4);
            const float4 a1 = *(const float4*)(vb + 1 * ZSTRIDE + ci4 * 4);
            const float4 a2 = *(const float4*)(vb + 2 * ZSTRIDE + ci4 * 4);
            const float4 a3 = *(const float4*)(vb + 3 * ZSTRIDE + ci4 * 4);
            const float a0v[4] = {a0.x, a0.y, a0.z, a0.w};
            const float a1v[4] = {a1.x, a1.y, a1.z, a1.w};
            const float a2v[4] = {a2.x, a2.y, a2.z, a2.w};
            const float a3v[4] = {a3.x, a3.y, a3.z, a3.w};
            #pragma unroll
            for (int c = 0; c < 4; ++c) {
                const unsigned long long xd0 = dup2(a0v[c]);
                const unsigned long long xd1 = dup2(a1v[c]);
                const unsigned long long xd2 = dup2(a2v[c]);
                const unsigned long long xd3 = dup2(a3v[c]);
                const ulonglong2* wr = (const ulonglong2*)&wtap[(ci4 * 4 + c) * 16];
                #pragma unroll
                for (int q = 0; q < 4; ++q) {
                    const ulonglong2 w = wr[q];   // 4 couts (2 packed pairs), warp-uniform
                    acc[0][2 * q]     = ffma2(xd0, w.x, acc[0][2 * q]);
                    acc[0][2 * q + 1] = ffma2(xd0, w.y, acc[0][2 * q + 1]);
                    acc[1][2 * q]     = ffma2(xd1, w.x, acc[1][2 * q]);
                    acc[1][2 * q + 1] = ffma2(xd1, w.y, acc[1][2 * q + 1]);
                    acc[2][2 * q]     = ffma2(xd2, w.x, acc[2][2 * q]);
                    acc[2][2 * q + 1] = ffma2(xd2, w.y, acc[2][2 * q + 1]);
                    acc[3][2 * q]     = ffma2(xd3, w.x, acc[3][2 * q]);
                    acc[3][2 * q + 1] = ffma2(xd3, w.y, acc[3][2 * q + 1]);
                }
            }
        }
    }

    // ---- store 4 voxels (guarded against tile overhang) ----
    const int gx = x0 + x, gy = y0 + y;
    if (gx < R && gy < R) {
        float* outbase = out + (size_t)b * N_TOTAL * 16;
        const size_t xybase = (size_t)(off + gx + gy * R);
        #pragma unroll
        for (int k = 0; k < 4; ++k) {
            const int gz = z0 + 4 * zh + k;
            if (gz < R) {
                ulonglong2* o = (ulonglong2*)(outbase +
                    (xybase + (size_t)gz * R * R) * 16);
                o[0] = make_ulonglong2(acc[k][0], acc[k][1]);
                o[1] = make_ulonglong2(acc[k][2], acc[k][3]);
                o[2] = make_ulonglong2(acc[k][4], acc[k][5]);
                o[3] = make_ulonglong2(acc[k][6], acc[k][7]);
            }
        }
    }
}

extern "C" void kernel_launch(void* const* d_in, const int* in_sizes, int n_in,
                              void* d_out, int out_size)
{
    const float* input  = (const float*)d_in[0];
    const float* weight = (const float*)d_in[1];
    const float* bias   = (const float*)d_in[2];
    float* out = (float*)d_out;

    cudaFuncSetAttribute(conv3d_v2_kernel,
                         cudaFuncAttributeMaxDynamicSharedMemorySize, SMEM_BYTES);
    dim3 grid(N_TILES, 2);
    conv3d_v2_kernel<<<grid, 128, SMEM_BYTES>>>(input, weight, bias, out);
}

// round 4
// speedup vs baseline: 1.5216x; 1.2158x over previous
#include <cuda_runtime.h>

// ---------------------------------------------------------------------------
// AbstractConv3D v3: v2 + latency hiding. One block per 8x8x8 tile, 128 thr,
// thread owns a z-quad of 4 voxels. Per tap: hoist all 16 input LDS.128 into
// registers (64 regs), fully unroll ci4 so ptxas pipelines weight-LDS/dup/FMA2.
// 16 output channels x 4 voxels as 32 packed f32x2 accumulators (fma.rn.f32x2).
// ---------------------------------------------------------------------------

#define N_TOTAL 1846083
#define N_TILES 4059      // sum over levels of ceil(R/8)^3
#define PAD     20        // floats per voxel in smem halo (16 data + 4 pad)

__constant__ int c_R[16]    = {16,18,20,22,25,27,30,34,38,42,47,52,58,64,72,80};
__constant__ int c_off[16]  = {0,4096,9928,17928,28576,44201,63884,90884,
                               130188,185060,259148,362971,503579,698691,960835,1334083};
__constant__ int c_Tdim[16] = {2,3,3,3,4,4,4,5,5,6,6,7,8,8,9,10};
__constant__ int c_tcum[16] = {8,35,62,89,153,217,281,406,531,747,963,1306,1818,2330,3059,4059};

__device__ __forceinline__ unsigned long long ffma2(unsigned long long a,
                                                    unsigned long long b,
                                                    unsigned long long c) {
    unsigned long long d;
    asm("fma.rn.f32x2 %0, %1, %2, %3;" : "=l"(d) : "l"(a), "l"(b), "l"(c));
    return d;
}
__device__ __forceinline__ unsigned long long dup2(float x) {
    unsigned long long r;
    asm("mov.b64 %0, {%1, %1};" : "=l"(r) : "f"(x));
    return r;
}
__device__ __forceinline__ unsigned long long pack2(float lo, float hi) {
    unsigned long long r;
    asm("mov.b64 %0, {%1, %2};" : "=l"(r) : "f"(lo), "f"(hi));
    return r;
}

#define SMEM_IN_FLOATS (1000 * PAD)           // 20000 floats = 80 KB
#define SMEM_W_FLOATS  6912                   // 27*16*16     = 27.6 KB
#define SMEM_BYTES     ((SMEM_IN_FLOATS + SMEM_W_FLOATS) * 4)

__global__ void __launch_bounds__(128, 2)
conv3d_v3_kernel(const float* __restrict__ input,
                 const float* __restrict__ weight,
                 const float* __restrict__ bias,
                 float* __restrict__ out)
{
    extern __shared__ float smem[];
    float* s_in = smem;                       // [1000][PAD]
    float* s_w  = smem + SMEM_IN_FLOATS;      // [27][16][16]

    const int t   = blockIdx.x;
    const int b   = blockIdx.y;
    const int tid = threadIdx.x;

    // tile -> level
    int l = 0;
    while (t >= c_tcum[l]) ++l;
    const int base  = l ? c_tcum[l - 1] : 0;
    int local = t - base;
    const int T   = c_Tdim[l];
    const int R   = c_R[l];
    const int off = c_off[l];
    const int tx  = local % T;
    local /= T;
    const int ty  = local % T;
    const int tz  = local / T;
    const int x0 = tx * 8, y0 = ty * 8, z0 = tz * 8;

    // ---- load halo (zeros outside grid = SAME zero padding) ----
    const float* inbase = input + (size_t)b * N_TOTAL * 16;
    for (int h = tid; h < 1000; h += 128) {
        const int hx = h % 10;
        const int hq = h / 10;
        const int hy = hq % 10;
        const int hz = hq / 10;
        const int gx = x0 - 1 + hx;
        const int gy = y0 - 1 + hy;
        const int gz = z0 - 1 + hz;
        float* dst = &s_in[h * PAD];
        if ((unsigned)gx < (unsigned)R && (unsigned)gy < (unsigned)R &&
            (unsigned)gz < (unsigned)R) {
            const float4* src = (const float4*)(inbase +
                (size_t)(off + gx + gy * R + gz * R * R) * 16);
            ((float4*)dst)[0] = src[0];
            *(float4*)(dst + 4)  = src[1];
            *(float4*)(dst + 8)  = src[2];
            *(float4*)(dst + 12) = src[3];
        } else {
            const float4 z4 = make_float4(0.f, 0.f, 0.f, 0.f);
            ((float4*)dst)[0] = z4;
            *(float4*)(dst + 4)  = z4;
            *(float4*)(dst + 8)  = z4;
            *(float4*)(dst + 12) = z4;
        }
    }
    // ---- load weights for this level ----
    {
        const float4* wsrc = (const float4*)(weight + (size_t)l * SMEM_W_FLOATS);
        float4* wdst = (float4*)s_w;
        for (int i = tid; i < SMEM_W_FLOATS / 4; i += 128) wdst[i] = wsrc[i];
    }
    __syncthreads();

    // ---- compute: thread (x, y, zh) owns voxels z = 4*zh + {0,1,2,3} ----
    const int x  = tid & 7;
    const int y  = (tid >> 3) & 7;
    const int zh = tid >> 6;          // 0 or 1

    unsigned long long acc[4][8];
    {
        const float* bp = bias + l * 16;
        #pragma unroll
        for (int j = 0; j < 8; ++j) {
            const unsigned long long bj = pack2(bp[2 * j], bp[2 * j + 1]);
            acc[0][j] = bj; acc[1][j] = bj; acc[2][j] = bj; acc[3][j] = bj;
        }
    }

    const int hbase = ((4 * zh + 1) * 100 + (y + 1) * 10 + (x + 1)) * PAD;
    const int ZSTRIDE = 100 * PAD;

    #pragma unroll 1
    for (int tap = 0; tap < 27; ++tap) {
        const int dz  = tap / 9;
        const int rem = tap - dz * 9;
        const int dy  = rem / 3;
        const int dx  = rem - dy * 3;
        const int noff = ((dz - 1) * 100 + (dy - 1) * 10 + (dx - 1)) * PAD;

        const float* vb   = s_in + hbase + noff;
        const float* wtap = s_w + tap * 256;

        // hoist ALL input loads for this tap: 16 independent LDS.128
        float4 A[4][4];   // [ci4][voxel]
        #pragma unroll
        for (int ci4 = 0; ci4 < 4; ++ci4) {
            #pragma unroll
            for (int v = 0; v < 4; ++v) {
                A[ci4][v] = *(const float4*)(vb + v * ZSTRIDE + ci4 * 4);
            }
        }

        #pragma unroll
        for (int ci4 = 0; ci4 < 4; ++ci4) {
            const float av[4][4] = {
                {A[ci4][0].x, A[ci4][0].y, A[ci4][0].z, A[ci4][0].w},
                {A[ci4][1].x, A[ci4][1].y, A[ci4][1].z, A[ci4][1].w},
                {A[ci4][2].x, A[ci4][2].y, A[ci4][2].z, A[ci4][2].w},
                {A[ci4][3].x, A[ci4][3].y, A[ci4][3].z, A[ci4][3].w}};
            #pragma unroll
            for (int c = 0; c < 4; ++c) {
                const unsigned long long xd0 = dup2(av[0][c]);
                const unsigned long long xd1 = dup2(av[1][c]);
                const unsigned long long xd2 = dup2(av[2][c]);
                const unsigned long long xd3 = dup2(av[3][c]);
                const ulonglong2* wr = (const ulonglong2*)&wtap[(ci4 * 4 + c) * 16];
                #pragma unroll
                for (int q = 0; q < 4; ++q) {
                    const ulonglong2 w = wr[q];   // warp-uniform broadcast
                    acc[0][2 * q]     = ffma2(xd0, w.x, acc[0][2 * q]);
                    acc[0][2 * q + 1] = ffma2(xd0, w.y, acc[0][2 * q + 1]);
                    acc[1][2 * q]     = ffma2(xd1, w.x, acc[1][2 * q]);
                    acc[1][2 * q + 1] = ffma2(xd1, w.y, acc[1][2 * q + 1]);
                    acc[2][2 * q]     = ffma2(xd2, w.x, acc[2][2 * q]);
                    acc[2][2 * q + 1] = ffma2(xd2, w.y, acc[2][2 * q + 1]);
                    acc[3][2 * q]     = ffma2(xd3, w.x, acc[3][2 * q]);
                    acc[3][2 * q + 1] = ffma2(xd3, w.y, acc[3][2 * q + 1]);
                }
            }
        }
    }

    // ---- store 4 voxels (guarded against tile overhang) ----
    const int gx = x0 + x, gy = y0 + y;
    if (gx < R && gy < R) {
        float* outbase = out + (size_t)b * N_TOTAL * 16;
        const size_t xybase = (size_t)(off + gx + gy * R);
        #pragma unroll
        for (int k = 0; k < 4; ++k) {
            const int gz = z0 + 4 * zh + k;
            if (gz < R) {
                ulonglong2* o = (ulonglong2*)(outbase +
                    (xybase + (size_t)gz * R * R) * 16);
                o[0] = make_ulonglong2(acc[k][0], acc[k][1]);
                o[1] = make_ulonglong2(acc[k][2], acc[k][3]);
                o[2] = make_ulonglong2(acc[k][4], acc[k][5]);
                o[3] = make_ulonglong2(acc[k][6], acc[k][7]);
            }
        }
    }
}

extern "C" void kernel_launch(void* const* d_in, const int* in_sizes, int n_in,
                              void* d_out, int out_size)
{
    const float* input  = (const float*)d_in[0];
    const float* weight = (const float*)d_in[1];
    const float* bias   = (const float*)d_in[2];
    float* out = (float*)d_out;

    cudaFuncSetAttribute(conv3d_v3_kernel,
                         cudaFuncAttributeMaxDynamicSharedMemorySize, SMEM_BYTES);
    dim3 grid(N_TILES, 2);
    conv3d_v3_kernel<<<grid, 128, SMEM_BYTES>>>(input, weight, bias, out);
}